// round 11
// baseline (speedup 1.0000x reference)
#include <cuda_runtime.h>
#include <cuda_bf16.h>

// ===================== table parameters =====================
#define TN      4096                  // table entries
#define T_LO    (-24.0f)              // t = log2(d^2); d in [2^-12, 32]
#define T_HI    (10.0f)
#define HT      ((T_HI - T_LO) / (float)TN)
#define INV_HT  ((float)TN / (T_HI - T_LO))

__device__ float  g_Hval[TN + 4];     // H at grid g = m-2, m in [0, TN+3]
__device__ float4 g_tab4[TN];         // g_tab4[k] = H at grid {k-1, k, k+1, k+2}

// ===================== build kernel =====================
// 4 warps/block, 2 entries/warp -> 8 entries/block, 513 blocks (oversubscribed grid)
#define BWARPS 4
#define BJT    2
#define BTHREADS (BWARPS * 32)
#define ENTRIES_PER_BLOCK (BWARPS * BJT)   // 8

__device__ __forceinline__ float fast_tanh(float x) {
    x = fminf(fmaxf(x, -15.0f), 15.0f);
    float e = __expf(2.0f * x);
    return 1.0f - __fdividef(2.0f, e + 1.0f);
}

__global__ __launch_bounds__(BTHREADS)
void build_table_kernel(
    const float* __restrict__ W1, const float* __restrict__ b1,
    const float* __restrict__ W2, const float* __restrict__ b2,
    const float* __restrict__ W3, const float* __restrict__ b3)
{
    __shared__ float h_s[ENTRIES_PER_BLOCK * 128];   // 4KB

    const int tid  = threadIdx.x;
    const int w    = tid >> 5;
    const int lane = tid & 31;

    // lane owns k = 4*lane + u, u in 0..3
    const float4 w1r0 = ((const float4*)W1)[lane];
    const float4 w1r1 = ((const float4*)(W1 + 128))[lane];
    const float4 w1r2 = ((const float4*)(W1 + 256))[lane];
    const float4 b1v  = ((const float4*)b1)[lane];

    const int ebase = blockIdx.x * ENTRIES_PER_BLOCK + w * BJT;

    // ---- features + layer 1 ----
    float invs[BJT];
    #pragma unroll
    for (int jl = 0; jl < BJT; ++jl) {
        int e = ebase + jl;
        float t  = T_LO + (float)(e - 2) * HT;    // grid g = e-2
        float d  = exp2f(0.5f * t);
        float dc = fmaxf(d, 0.01f);
        float inv = 1.0f / dc;
        invs[jl] = inv;
        float inv2 = inv * inv;

        float4 pre;
        pre.x = fmaf(d, w1r0.x, fmaf(inv, w1r1.x, fmaf(inv2, w1r2.x, b1v.x)));
        pre.y = fmaf(d, w1r0.y, fmaf(inv, w1r1.y, fmaf(inv2, w1r2.y, b1v.y)));
        pre.z = fmaf(d, w1r0.z, fmaf(inv, w1r1.z, fmaf(inv2, w1r2.z, b1v.z)));
        pre.w = fmaf(d, w1r0.w, fmaf(inv, w1r1.w, fmaf(inv2, w1r2.w, b1v.w)));

        float4 h;
        h.x = fast_tanh(pre.x);
        h.y = fast_tanh(pre.y);
        h.z = fast_tanh(pre.z);
        h.w = fast_tanh(pre.w);
        ((float4*)(h_s + (w * BJT + jl) * 128))[lane] = h;
    }
    __syncwarp();

    // ---- layer 2: software-pipelined, W2 straight from global (L1-resident) ----
    const float4* W2v = (const float4*)W2;        // row c: W2v[c*32 + lane]
    float4 acc[BJT];
    #pragma unroll
    for (int jl = 0; jl < BJT; ++jl) acc[jl] = make_float4(0.f, 0.f, 0.f, 0.f);

    float4 wv[4];
    #pragma unroll
    for (int u = 0; u < 4; ++u) wv[u] = W2v[u * 32 + lane];

    #pragma unroll 4
    for (int c4 = 0; c4 < 32; ++c4) {
        float4 nxt[4];
        const int cn = (c4 + 1) & 31;             // last prefetch wraps (harmless)
        #pragma unroll
        for (int u = 0; u < 4; ++u) nxt[u] = W2v[(cn * 4 + u) * 32 + lane];

        #pragma unroll
        for (int jl = 0; jl < BJT; ++jl) {
            float4 hv = ((const float4*)(h_s + (w * BJT + jl) * 128))[c4];  // broadcast
            acc[jl].x = fmaf(hv.x, wv[0].x, acc[jl].x);
            acc[jl].y = fmaf(hv.x, wv[0].y, acc[jl].y);
            acc[jl].z = fmaf(hv.x, wv[0].z, acc[jl].z);
            acc[jl].w = fmaf(hv.x, wv[0].w, acc[jl].w);
            acc[jl].x = fmaf(hv.y, wv[1].x, acc[jl].x);
            acc[jl].y = fmaf(hv.y, wv[1].y, acc[jl].y);
            acc[jl].z = fmaf(hv.y, wv[1].z, acc[jl].z);
            acc[jl].w = fmaf(hv.y, wv[1].w, acc[jl].w);
            acc[jl].x = fmaf(hv.z, wv[2].x, acc[jl].x);
            acc[jl].y = fmaf(hv.z, wv[2].y, acc[jl].y);
            acc[jl].z = fmaf(hv.z, wv[2].z, acc[jl].z);
            acc[jl].w = fmaf(hv.z, wv[2].w, acc[jl].w);
            acc[jl].x = fmaf(hv.w, wv[3].x, acc[jl].x);
            acc[jl].y = fmaf(hv.w, wv[3].y, acc[jl].y);
            acc[jl].z = fmaf(hv.w, wv[3].z, acc[jl].z);
            acc[jl].w = fmaf(hv.w, wv[3].w, acc[jl].w);
        }
        #pragma unroll
        for (int u = 0; u < 4; ++u) wv[u] = nxt[u];
    }

    // ---- layer 3 + warp reduce + write ----
    const float4 b2v = ((const float4*)b2)[lane];
    const float4 w3v = ((const float4*)W3)[lane];
    const float  b3v = b3[0];

    #pragma unroll
    for (int jl = 0; jl < BJT; ++jl) {
        float h2x = fast_tanh(acc[jl].x + b2v.x);
        float h2y = fast_tanh(acc[jl].y + b2v.y);
        float h2z = fast_tanh(acc[jl].z + b2v.z);
        float h2w = fast_tanh(acc[jl].w + b2v.w);
        float s = fmaf(h2x, w3v.x, fmaf(h2y, w3v.y, fmaf(h2z, w3v.z, h2w * w3v.w)));
        #pragma unroll
        for (int off = 16; off > 0; off >>= 1)
            s += __shfl_xor_sync(0xffffffffu, s, off);
        if (lane == 0) {
            int e = ebase + jl;
            if (e < TN + 4)
                g_Hval[e] = (s + b3v) * invs[jl];
        }
    }
}

// ===================== pack kernel =====================
__global__ void pack_table_kernel() {
    int k = blockIdx.x * blockDim.x + threadIdx.x;
    if (k < TN)
        g_tab4[k] = make_float4(g_Hval[k + 1], g_Hval[k + 2],
                                g_Hval[k + 3], g_Hval[k + 4]);
}

// ===================== force kernel =====================
__global__ __launch_bounds__(256)
void force_kernel(const float* __restrict__ pos, float* __restrict__ out, int N)
{
    __shared__ float4 pos4[1024];
    const int tid = threadIdx.x;
    const int b   = blockIdx.y;
    const float* pos_b = pos + (size_t)b * N * 3;

    for (int idx = tid; idx < N; idx += 256)
        pos4[idx] = make_float4(pos_b[idx * 3 + 0], pos_b[idx * 3 + 1],
                                pos_b[idx * 3 + 2], 0.0f);
    __syncthreads();

    const int w    = tid >> 5;
    const int lane = tid & 31;
    const int i    = blockIdx.x * 8 + w;     // one i per warp
    const float4 pi = pos4[i];

    float fx = 0.0f, fy = 0.0f, fz = 0.0f;

    #pragma unroll 8
    for (int jj = 0; jj < 32; ++jj) {
        int j = jj * 32 + lane;
        float4 pj = pos4[j];
        float dx = pi.x - pj.x;
        float dy = pi.y - pj.y;
        float dz = pi.z - pj.z;
        float s = fmaf(dx, dx, fmaf(dy, dy, dz * dz));
        float t = __log2f(s);                         // s=0 -> -inf -> clamps
        float u = (t - T_LO) * INV_HT;
        u = fminf(fmaxf(u, 0.0f), (float)TN - 1.001f);
        int   k = (int)u;
        float f = u - (float)k;
        float4 hv = __ldg(&g_tab4[k]);                // H at grid k-1..k+2
        // Catmull-Rom
        float c = hv.y + 0.5f * f * ((hv.z - hv.x) +
                  f * ((2.0f * hv.x - 5.0f * hv.y + 4.0f * hv.z - hv.w) +
                  f * (3.0f * (hv.y - hv.z) + (hv.w - hv.x))));
        fx = fmaf(c, dx, fx);
        fy = fmaf(c, dy, fy);
        fz = fmaf(c, dz, fz);
    }

    #pragma unroll
    for (int off = 16; off > 0; off >>= 1) {
        fx += __shfl_xor_sync(0xffffffffu, fx, off);
        fy += __shfl_xor_sync(0xffffffffu, fy, off);
        fz += __shfl_xor_sync(0xffffffffu, fz, off);
    }
    if (lane == 0) {
        float* o = out + ((size_t)b * N + i) * 3;
        o[0] = fx; o[1] = fy; o[2] = fz;
    }
}

// ===================== launch =====================
extern "C" void kernel_launch(void* const* d_in, const int* in_sizes, int n_in,
                              void* d_out, int out_size) {
    const float* pos = (const float*)d_in[0];
    const float* W1  = (const float*)d_in[1];
    const float* b1  = (const float*)d_in[2];
    const float* W2  = (const float*)d_in[3];
    const float* b2  = (const float*)d_in[4];
    const float* W3  = (const float*)d_in[5];
    const float* b3  = (const float*)d_in[6];
    float* out = (float*)d_out;

    const int N = 1024;
    const int B = in_sizes[0] / (N * 3);

    const int nblk = (TN + 4 + ENTRIES_PER_BLOCK - 1) / ENTRIES_PER_BLOCK;  // 513
    build_table_kernel<<<nblk, BTHREADS>>>(W1, b1, W2, b2, W3, b3);
    pack_table_kernel<<<TN / 256, 256>>>();
    force_kernel<<<dim3(N / 8, B), 256>>>(pos, out, N);
}